// round 1
// baseline (speedup 1.0000x reference)
#include <cuda_runtime.h>
#include <cstdint>

#define NN 100000
#define EE 1600000
#define FIN 256
#define HID 128
#define NCLS 40

// ---------------- scratch (device globals; no allocation allowed) ----------------
__device__ float g_csrc[NN];
__device__ float g_cdst[NN];
__device__ float g_bufA[(size_t)NN * HID];
__device__ float g_bufB[(size_t)NN * HID];

// ---------------- zero (float4) ----------------
__global__ void zero4_kernel(float4* __restrict__ p, int n4) {
    int i = blockIdx.x * blockDim.x + threadIdx.x;
    if (i < n4) p[i] = make_float4(0.f, 0.f, 0.f, 0.f);
}

// ---------------- degree accumulation ----------------
__global__ void deg_kernel(const int* __restrict__ src, const int* __restrict__ dst,
                           float* __restrict__ cs, float* __restrict__ cd, int e) {
    int i = blockIdx.x * blockDim.x + threadIdx.x;
    if (i < e) {
        atomicAdd(&cs[src[i]], 1.f);
        atomicAdd(&cd[dst[i]], 1.f);
    }
}

__global__ void norm_kernel(float* __restrict__ cs, float* __restrict__ cd, int n) {
    int i = blockIdx.x * blockDim.x + threadIdx.x;
    if (i < n) {
        cs[i] = rsqrtf(fmaxf(cs[i], 1.f));
        cd[i] = rsqrtf(fmaxf(cd[i], 1.f));
    }
}

// ---------------- tiled GEMM: out[row][c] = (sum_k A[row][k] W[k][c]) * rowscale[row]
// A: [n, K_DIM], W: [K_DIM, 128], out: [n, 128]
// block: 64 rows x 128 cols, blockDim (32,8), per-thread 8 rows x 4 cols.
template <int K_DIM>
__global__ void __launch_bounds__(256) gemm128_kernel(
    const float* __restrict__ A, const float* __restrict__ W,
    const float* __restrict__ rowscale, float* __restrict__ out, int n) {
    __shared__ float As[32][65];   // [kk][row], padded -> conflict-free transpose store
    __shared__ float Ws[32][128];  // [kk][col]

    const int tx = threadIdx.x;            // 0..31 -> col group (4 cols)
    const int ty = threadIdx.y;            // 0..7  -> row phase
    const int t = ty * 32 + tx;
    const int row0 = blockIdx.x * 64;

    float acc[8][4];
#pragma unroll
    for (int i = 0; i < 8; i++)
#pragma unroll
        for (int j = 0; j < 4; j++) acc[i][j] = 0.f;

    for (int k0 = 0; k0 < K_DIM; k0 += 32) {
        // load A tile (64 rows x 32 k), coalesced over k, stored transposed
#pragma unroll
        for (int i = 0; i < 8; i++) {
            int j = t + i * 256;       // 0..2047
            int r = j >> 5, kk = j & 31;
            int grow = row0 + r;
            As[kk][r] = (grow < n) ? A[(size_t)grow * K_DIM + k0 + kk] : 0.f;
        }
        // load W tile (32 x 128), coalesced
#pragma unroll
        for (int i = 0; i < 16; i++) {
            int j = t + i * 256;       // 0..4095
            int kk = j >> 7, c = j & 127;
            Ws[kk][c] = W[(size_t)(k0 + kk) * 128 + c];
        }
        __syncthreads();
#pragma unroll
        for (int kk = 0; kk < 32; kk++) {
            float4 w = *reinterpret_cast<const float4*>(&Ws[kk][tx * 4]);
#pragma unroll
            for (int i = 0; i < 8; i++) {
                float xv = As[kk][ty + 8 * i];   // warp-broadcast
                acc[i][0] += xv * w.x;
                acc[i][1] += xv * w.y;
                acc[i][2] += xv * w.z;
                acc[i][3] += xv * w.w;
            }
        }
        __syncthreads();
    }
#pragma unroll
    for (int i = 0; i < 8; i++) {
        int grow = row0 + ty + 8 * i;
        if (grow < n) {
            float s = rowscale[grow];
            float4 v = make_float4(acc[i][0] * s, acc[i][1] * s, acc[i][2] * s, acc[i][3] * s);
            *reinterpret_cast<float4*>(&out[(size_t)grow * 128 + tx * 4]) = v;
        }
    }
}

// ---------------- edge scatter: out[dst] += h[src]  (128 floats, warp per edge) ----
__global__ void scatter128_kernel(const float* __restrict__ h, const int* __restrict__ src,
                                  const int* __restrict__ dst, float* __restrict__ out, int e) {
    int g = blockIdx.x * blockDim.x + threadIdx.x;
    int edge = g >> 5;
    int lane = g & 31;
    if (edge >= e) return;
    int s = src[edge];   // broadcast within warp
    int d = dst[edge];
    float4 v = *reinterpret_cast<const float4*>(&h[(size_t)s * 128 + lane * 4]);
    float* p = &out[(size_t)d * 128 + lane * 4];
    asm volatile("red.global.add.v4.f32 [%0], {%1, %2, %3, %4};"
                 :: "l"(p), "f"(v.x), "f"(v.y), "f"(v.z), "f"(v.w)
                 : "memory");
}

// ---------------- pointwise: out = (agg * cdst[row] + bias[c]) [relu] --------------
template <bool RELU>
__global__ void axpb_kernel(const float* __restrict__ agg, const float* __restrict__ cdst,
                            const float* __restrict__ bias, float* __restrict__ out, int n) {
    int idx = blockIdx.x * blockDim.x + threadIdx.x;  // over n*32 float4s
    if (idx >= n * 32) return;
    int row = idx >> 5;
    int c4 = idx & 31;
    float s = cdst[row];
    float4 a = reinterpret_cast<const float4*>(agg)[idx];
    float4 b = *reinterpret_cast<const float4*>(&bias[c4 * 4]);
    float4 r;
    r.x = a.x * s + b.x;
    r.y = a.y * s + b.y;
    r.z = a.z * s + b.z;
    r.w = a.w * s + b.w;
    if (RELU) {
        r.x = fmaxf(r.x, 0.f); r.y = fmaxf(r.y, 0.f);
        r.z = fmaxf(r.z, 0.f); r.w = fmaxf(r.w, 0.f);
    }
    reinterpret_cast<float4*>(out)[idx] = r;
}

// ---------------- classifier: logits = relu(h) @ Wc + bc ---------------------------
// block handles 64 rows; blockDim (64,4): 4 rows per chunk, tx<40 compute cols.
__global__ void __launch_bounds__(256) classifier_kernel(
    const float* __restrict__ h, const float* __restrict__ Wc,
    const float* __restrict__ bc, float* __restrict__ out, int n) {
    __shared__ float Ws[128][NCLS];   // 20 KB
    __shared__ float hs[4][128];
    __shared__ float bs[NCLS];

    const int tx = threadIdx.x, ty = threadIdx.y;
    const int t = ty * 64 + tx;
    for (int j = t; j < 128 * NCLS; j += 256) Ws[j / NCLS][j % NCLS] = Wc[j];
    if (t < NCLS) bs[t] = bc[t];

    const int row0 = blockIdx.x * 64;
    for (int r0 = 0; r0 < 64; r0 += 4) {
        __syncthreads();
        for (int j = t; j < 512; j += 256) {
            int rr = j >> 7, k = j & 127;
            int grow = row0 + r0 + rr;
            hs[rr][k] = (grow < n) ? fmaxf(h[(size_t)grow * 128 + k], 0.f) : 0.f;
        }
        __syncthreads();
        if (tx < NCLS) {
            float acc = bs[tx];
#pragma unroll 16
            for (int k = 0; k < 128; k++) acc += hs[ty][k] * Ws[k][tx];
            int grow = row0 + r0 + ty;
            if (grow < n) out[(size_t)grow * NCLS + tx] = acc;
        }
    }
}

// ---------------- launch ------------------------------------------------------------
extern "C" void kernel_launch(void* const* d_in, const int* in_sizes, int n_in,
                              void* d_out, int out_size) {
    const float* x  = (const float*)d_in[0];
    const int*   src = (const int*)d_in[1];
    const int*   dst = (const int*)d_in[2];
    const float* W0 = (const float*)d_in[3];
    const float* b0 = (const float*)d_in[4];
    const float* W1 = (const float*)d_in[5];
    const float* b1 = (const float*)d_in[6];
    const float* Wc = (const float*)d_in[7];
    const float* bc = (const float*)d_in[8];
    float* out = (float*)d_out;
    float* out_h = out;                         // [N,128]
    float* out_logits = out + (size_t)NN * HID; // [N,40]

    float *pCsrc, *pCdst, *pA, *pB;
    cudaGetSymbolAddress((void**)&pCsrc, g_csrc);
    cudaGetSymbolAddress((void**)&pCdst, g_cdst);
    cudaGetSymbolAddress((void**)&pA, g_bufA);
    cudaGetSymbolAddress((void**)&pB, g_bufB);

    const int n4_c = NN / 4;                    // 25000 float4 (NN % 4 == 0)
    const int n4_h = NN * (HID / 4);            // 3.2M float4
    const int TB = 256;

    // degree norms
    zero4_kernel<<<(n4_c + TB - 1) / TB, TB>>>((float4*)pCsrc, n4_c);
    zero4_kernel<<<(n4_c + TB - 1) / TB, TB>>>((float4*)pCdst, n4_c);
    deg_kernel<<<(EE + TB - 1) / TB, TB>>>(src, dst, pCsrc, pCdst, EE);
    norm_kernel<<<(NN + TB - 1) / TB, TB>>>(pCsrc, pCdst, NN);

    dim3 gblk(32, 8);
    const int ngemm = (NN + 63) / 64;           // 1563

    // layer 0: bufA = (x @ W0) * c_src
    gemm128_kernel<FIN><<<ngemm, gblk>>>(x, W0, pCsrc, pA, NN);
    // bufB = scatter-add bufA[src] -> dst
    zero4_kernel<<<(n4_h + TB - 1) / TB, TB>>>((float4*)pB, n4_h);
    scatter128_kernel<<<(EE * 32 + TB - 1) / TB, TB>>>(pA, src, dst, pB, EE);
    // bufA = relu(bufB * c_dst + b0)
    axpb_kernel<true><<<(NN * 32 + TB - 1) / TB, TB>>>(pB, pCdst, b0, pA, NN);

    // layer 1: bufB = (bufA @ W1) * c_src
    gemm128_kernel<HID><<<ngemm, gblk>>>(pA, W1, pCsrc, pB, NN);
    zero4_kernel<<<(n4_h + TB - 1) / TB, TB>>>((float4*)pA, n4_h);
    scatter128_kernel<<<(EE * 32 + TB - 1) / TB, TB>>>(pB, src, dst, pA, EE);
    // h = bufA * c_dst + b1   (no relu; this is output #1)
    axpb_kernel<false><<<(NN * 32 + TB - 1) / TB, TB>>>(pA, pCdst, b1, out_h, NN);

    // logits = relu(h) @ Wc + bc
    dim3 cblk(64, 4);
    classifier_kernel<<<ngemm, cblk>>>(out_h, Wc, bc, out_logits, NN);
}

// round 3
// speedup vs baseline: 1.5563x; 1.5563x over previous
#include <cuda_runtime.h>
#include <cstdint>

#define NN 100000
#define EE 1600000
#define FIN 256
#define HID 128
#define NCLS 40
#define NB_SCAN 98   // ceil(NN/1024)

// ---------------- scratch (device globals; no allocation allowed) ----------------
__device__ float g_csrc[NN];
__device__ float g_cdst[NN];
__device__ int   g_cnt_s[NN];
__device__ int   g_cnt_d[NN];
__device__ int   g_rowptr[NN + 1];
__device__ int   g_pos[NN];
__device__ int   g_bsum[128];
__device__ int   g_esrc[EE];
__device__ float g_bufA[(size_t)NN * HID];
__device__ float g_bufB[(size_t)NN * HID];

// ---------------- zero ints ----------------
__global__ void zeroi_kernel(int* __restrict__ p, int n) {
    int i = blockIdx.x * blockDim.x + threadIdx.x;
    if (i < n) p[i] = 0;
}

// ---------------- degree histogram (int) ----------------
__global__ void deg_kernel(const int* __restrict__ src, const int* __restrict__ dst,
                           int* __restrict__ cs, int* __restrict__ cd, int e) {
    int i = blockIdx.x * blockDim.x + threadIdx.x;
    if (i < e) {
        atomicAdd(&cs[src[i]], 1);
        atomicAdd(&cd[dst[i]], 1);
    }
}

__global__ void norm_kernel(const int* __restrict__ cs, const int* __restrict__ cd,
                            float* __restrict__ ncs, float* __restrict__ ncd, int n) {
    int i = blockIdx.x * blockDim.x + threadIdx.x;
    if (i < n) {
        ncs[i] = rsqrtf(fmaxf((float)cs[i], 1.f));
        ncd[i] = rsqrtf(fmaxf((float)cd[i], 1.f));
    }
}

// ---------------- scan stage 1: per-block exclusive scan of 1024 ints --------------
__global__ void __launch_bounds__(256) scan_local_kernel(
    const int* __restrict__ in, int* __restrict__ out, int* __restrict__ bsum, int n) {
    __shared__ int wsum[8];
    int t = threadIdx.x;
    int base = blockIdx.x * 1024 + t * 4;
    int v[4];
#pragma unroll
    for (int i = 0; i < 4; i++) v[i] = (base + i < n) ? in[base + i] : 0;
    int tsum = v[0] + v[1] + v[2] + v[3];
    int lane = t & 31, wid = t >> 5;
    int inc = tsum;
#pragma unroll
    for (int off = 1; off < 32; off <<= 1) {
        int tmp = __shfl_up_sync(0xffffffffu, inc, off);
        if (lane >= off) inc += tmp;
    }
    if (lane == 31) wsum[wid] = inc;
    __syncthreads();
    if (t < 8) {
        int ws = wsum[t];
#pragma unroll
        for (int off = 1; off < 8; off <<= 1) {
            int tmp = __shfl_up_sync(0xffu, ws, off);
            if (t >= off) ws += tmp;
        }
        wsum[t] = ws;
    }
    __syncthreads();
    int excl = inc - tsum + (wid > 0 ? wsum[wid - 1] : 0);
    int run = excl;
#pragma unroll
    for (int i = 0; i < 4; i++) {
        if (base + i < n) out[base + i] = run;
        run += v[i];
    }
    if (t == 255) bsum[blockIdx.x] = wsum[7];
}

// ---------------- scan stage 2: exclusive scan of block sums (1 block) -------------
__global__ void scan_bsum_kernel(int* __restrict__ bsum, int nb) {
    __shared__ int s[128];
    int t = threadIdx.x;
    int v = (t < nb) ? bsum[t] : 0;
    s[t] = v;
    __syncthreads();
    for (int off = 1; off < 128; off <<= 1) {
        int tmp = (t >= off) ? s[t - off] : 0;
        __syncthreads();
        s[t] += tmp;
        __syncthreads();
    }
    if (t < nb) bsum[t] = s[t] - v;
}

// ---------------- scan stage 3: add offsets, init pos, finalize rowptr -------------
__global__ void scan_add_kernel(int* __restrict__ rowptr, int* __restrict__ pos,
                                const int* __restrict__ bsum, int n) {
    int i = blockIdx.x * blockDim.x + threadIdx.x;
    if (i < n) {
        int v = rowptr[i] + bsum[i >> 10];
        rowptr[i] = v;
        pos[i] = v;
    }
    if (i == 0) rowptr[n] = EE;
}

// ---------------- CSR bucket fill ----------------
__global__ void fill_kernel(const int* __restrict__ src, const int* __restrict__ dst,
                            int* __restrict__ pos, int* __restrict__ esrc, int e) {
    int i = blockIdx.x * blockDim.x + threadIdx.x;
    if (i < e) {
        int p = atomicAdd(&pos[dst[i]], 1);
        esrc[p] = src[i];
    }
}

// ---------------- atomic-free aggregation: out[d] = agg(h[srcs])*cdst[d] + b -------
template <bool RELU>
__global__ void __launch_bounds__(256) agg_kernel(
    const float* __restrict__ h, const int* __restrict__ esrc,
    const int* __restrict__ rowptr, const float* __restrict__ cdst,
    const float* __restrict__ bias, float* __restrict__ out, int n) {
    int g = blockIdx.x * blockDim.x + threadIdx.x;
    int w = g >> 5;
    int lane = g & 31;
    if (w >= n) return;
    int beg = rowptr[w];
    int end = rowptr[w + 1];
    float4 acc = make_float4(0.f, 0.f, 0.f, 0.f);
    int e = beg;
    for (; e + 4 <= end; e += 4) {
        int s0 = __ldg(&esrc[e]);
        int s1 = __ldg(&esrc[e + 1]);
        int s2 = __ldg(&esrc[e + 2]);
        int s3 = __ldg(&esrc[e + 3]);
        float4 v0 = *((const float4*)(h + (size_t)s0 * 128) + lane);
        float4 v1 = *((const float4*)(h + (size_t)s1 * 128) + lane);
        float4 v2 = *((const float4*)(h + (size_t)s2 * 128) + lane);
        float4 v3 = *((const float4*)(h + (size_t)s3 * 128) + lane);
        acc.x += (v0.x + v1.x) + (v2.x + v3.x);
        acc.y += (v0.y + v1.y) + (v2.y + v3.y);
        acc.z += (v0.z + v1.z) + (v2.z + v3.z);
        acc.w += (v0.w + v1.w) + (v2.w + v3.w);
    }
    for (; e < end; e++) {
        int s = __ldg(&esrc[e]);
        float4 v = *((const float4*)(h + (size_t)s * 128) + lane);
        acc.x += v.x; acc.y += v.y; acc.z += v.z; acc.w += v.w;
    }
    float c = cdst[w];
    float4 b = ((const float4*)bias)[lane];
    float4 r = make_float4(acc.x * c + b.x, acc.y * c + b.y,
                           acc.z * c + b.z, acc.w * c + b.w);
    if (RELU) {
        r.x = fmaxf(r.x, 0.f); r.y = fmaxf(r.y, 0.f);
        r.z = fmaxf(r.z, 0.f); r.w = fmaxf(r.w, 0.f);
    }
    ((float4*)out)[(size_t)w * 32 + lane] = r;
}

// ---------------- tiled GEMM: out[row][c] = (sum_k A[row][k] W[k][c]) * rowscale[row]
template <int K_DIM>
__global__ void __launch_bounds__(256) gemm128_kernel(
    const float* __restrict__ A, const float* __restrict__ W,
    const float* __restrict__ rowscale, float* __restrict__ out, int n) {
    __shared__ float As[32][65];
    __shared__ float Ws[32][128];

    const int tx = threadIdx.x;
    const int ty = threadIdx.y;
    const int t = ty * 32 + tx;
    const int row0 = blockIdx.x * 64;

    float acc[8][4];
#pragma unroll
    for (int i = 0; i < 8; i++)
#pragma unroll
        for (int j = 0; j < 4; j++) acc[i][j] = 0.f;

    for (int k0 = 0; k0 < K_DIM; k0 += 32) {
#pragma unroll
        for (int i = 0; i < 8; i++) {
            int j = t + i * 256;
            int r = j >> 5, kk = j & 31;
            int grow = row0 + r;
            As[kk][r] = (grow < n) ? A[(size_t)grow * K_DIM + k0 + kk] : 0.f;
        }
#pragma unroll
        for (int i = 0; i < 16; i++) {
            int j = t + i * 256;
            int kk = j >> 7, c = j & 127;
            Ws[kk][c] = W[(size_t)(k0 + kk) * 128 + c];
        }
        __syncthreads();
#pragma unroll
        for (int kk = 0; kk < 32; kk++) {
            float4 w = *reinterpret_cast<const float4*>(&Ws[kk][tx * 4]);
#pragma unroll
            for (int i = 0; i < 8; i++) {
                float xv = As[kk][ty + 8 * i];
                acc[i][0] += xv * w.x;
                acc[i][1] += xv * w.y;
                acc[i][2] += xv * w.z;
                acc[i][3] += xv * w.w;
            }
        }
        __syncthreads();
    }
#pragma unroll
    for (int i = 0; i < 8; i++) {
        int grow = row0 + ty + 8 * i;
        if (grow < n) {
            float s = rowscale[grow];
            float4 v = make_float4(acc[i][0] * s, acc[i][1] * s, acc[i][2] * s, acc[i][3] * s);
            *reinterpret_cast<float4*>(&out[(size_t)grow * 128 + tx * 4]) = v;
        }
    }
}

// ---------------- classifier: logits = relu(h) @ Wc + bc ---------------------------
// 320 threads: t -> (row = t/40, col = t%40); 100% lane utilization.
__global__ void __launch_bounds__(320) classifier_kernel(
    const float* __restrict__ h, const float* __restrict__ Wc,
    const float* __restrict__ bc, float* __restrict__ out, int n) {
    __shared__ float Ws[128][41];
    __shared__ float hs[8][132];
    __shared__ float bs[NCLS];

    const int t = threadIdx.x;
    for (int j = t; j < 128 * NCLS; j += 320) Ws[j / NCLS][j % NCLS] = Wc[j];
    if (t < NCLS) bs[t] = bc[t];

    const int row0 = blockIdx.x * 64;
    const int r = t / NCLS;       // 0..7
    const int c = t % NCLS;       // 0..39
    for (int rr0 = 0; rr0 < 64; rr0 += 8) {
        __syncthreads();
        for (int j = t; j < 8 * 128; j += 320) {
            int lr = j >> 7, k = j & 127;
            int grow = row0 + rr0 + lr;
            hs[lr][k] = (grow < n) ? fmaxf(h[(size_t)grow * 128 + k], 0.f) : 0.f;
        }
        __syncthreads();
        float acc = bs[c];
#pragma unroll 8
        for (int k = 0; k < 128; k++) acc += hs[r][k] * Ws[k][c];
        int grow = row0 + rr0 + r;
        if (grow < n) out[(size_t)grow * NCLS + c] = acc;
    }
}

// ---------------- launch ------------------------------------------------------------
extern "C" void kernel_launch(void* const* d_in, const int* in_sizes, int n_in,
                              void* d_out, int out_size) {
    const float* x   = (const float*)d_in[0];
    const int*   src = (const int*)d_in[1];
    const int*   dst = (const int*)d_in[2];
    const float* W0  = (const float*)d_in[3];
    const float* b0  = (const float*)d_in[4];
    const float* W1  = (const float*)d_in[5];
    const float* b1  = (const float*)d_in[6];
    const float* Wc  = (const float*)d_in[7];
    const float* bc  = (const float*)d_in[8];
    float* out = (float*)d_out;
    float* out_h = out;                          // [N,128]
    float* out_logits = out + (size_t)NN * HID;  // [N,40]

    float *pCsrc, *pCdst, *pA, *pB;
    int *pCntS, *pCntD, *pRow, *pPos, *pBsum, *pEsrc;
    cudaGetSymbolAddress((void**)&pCsrc, g_csrc);
    cudaGetSymbolAddress((void**)&pCdst, g_cdst);
    cudaGetSymbolAddress((void**)&pA, g_bufA);
    cudaGetSymbolAddress((void**)&pB, g_bufB);
    cudaGetSymbolAddress((void**)&pCntS, g_cnt_s);
    cudaGetSymbolAddress((void**)&pCntD, g_cnt_d);
    cudaGetSymbolAddress((void**)&pRow, g_rowptr);
    cudaGetSymbolAddress((void**)&pPos, g_pos);
    cudaGetSymbolAddress((void**)&pBsum, g_bsum);
    cudaGetSymbolAddress((void**)&pEsrc, g_esrc);

    const int TB = 256;

    // ---- degree norms + CSR build (once; shared by both layers) ----
    zeroi_kernel<<<(NN + TB - 1) / TB, TB>>>(pCntS, NN);
    zeroi_kernel<<<(NN + TB - 1) / TB, TB>>>(pCntD, NN);
    deg_kernel<<<(EE + TB - 1) / TB, TB>>>(src, dst, pCntS, pCntD, EE);
    norm_kernel<<<(NN + TB - 1) / TB, TB>>>(pCntS, pCntD, pCsrc, pCdst, NN);
    scan_local_kernel<<<NB_SCAN, 256>>>(pCntD, pRow, pBsum, NN);
    scan_bsum_kernel<<<1, 128>>>(pBsum, NB_SCAN);
    scan_add_kernel<<<(NN + TB - 1) / TB, TB>>>(pRow, pPos, pBsum, NN);
    fill_kernel<<<(EE + TB - 1) / TB, TB>>>(src, dst, pPos, pEsrc, EE);

    dim3 gblk(32, 8);
    const int ngemm = (NN + 63) / 64;        // 1563
    const int nagg = (NN * 32 + TB - 1) / TB;

    // ---- layer 0: bufA = (x @ W0) * c_src; bufB = relu(agg(bufA)*c_dst + b0) ----
    gemm128_kernel<FIN><<<ngemm, gblk>>>(x, W0, pCsrc, pA, NN);
    agg_kernel<true><<<nagg, TB>>>(pA, pEsrc, pRow, pCdst, b0, pB, NN);

    // ---- layer 1: bufA = (bufB @ W1) * c_src; out_h = agg(bufA)*c_dst + b1 ----
    gemm128_kernel<HID><<<ngemm, gblk>>>(pB, W1, pCsrc, pA, NN);
    agg_kernel<false><<<nagg, TB>>>(pA, pEsrc, pRow, pCdst, b1, out_h, NN);

    // ---- logits = relu(h) @ Wc + bc ----
    classifier_kernel<<<ngemm, 320>>>(out_h, Wc, bc, out_logits, NN);
}

// round 7
// speedup vs baseline: 2.4837x; 1.5959x over previous
#include <cuda_runtime.h>
#include <cstdint>

#define NN 100000
#define EE 1600000
#define FIN 256
#define HID 128
#define NCLS 40
#define NB_SCAN 98   // ceil(NN/1024)

// ---------------- scratch (device globals; no allocation allowed) ----------------
__device__ float g_csrc[NN];
__device__ float g_cdst[NN];
__device__ int   g_cnt_s[NN];
__device__ int   g_cnt_d[NN];
__device__ int   g_rowptr[NN + 1];
__device__ int   g_pos[NN];
__device__ int   g_bsum[128];
__device__ int   g_esrc[EE];
__device__ float g_bufA[(size_t)NN * HID];
__device__ float g_bufB[(size_t)NN * HID];

// ---------------- mma.sync tf32 helpers (baseline PTX, compiles at compute_103) ---
__device__ __forceinline__ uint32_t f2tf32(float x) {
    uint32_t r;
    asm("cvt.rna.tf32.f32 %0, %1;" : "=r"(r) : "f"(x));
    return r;
}
__device__ __forceinline__ void mma_tf32(float* d, const uint32_t* a, const uint32_t* b) {
    asm volatile(
        "mma.sync.aligned.m16n8k8.row.col.f32.tf32.tf32.f32 "
        "{%0,%1,%2,%3}, {%4,%5,%6,%7}, {%8,%9}, {%0,%1,%2,%3};"
        : "+f"(d[0]), "+f"(d[1]), "+f"(d[2]), "+f"(d[3])
        : "r"(a[0]), "r"(a[1]), "r"(a[2]), "r"(a[3]), "r"(b[0]), "r"(b[1]));
}

// ============ HMMA tf32 GEMM: out[r][c] = (A[r][:] @ W[:][c]) * rowscale[r] ========
// CTA tile 128x128; 8 warps (2x4); warp tile 64x32; K chunked by 32.
// smem strides chosen for zero-conflict fragment reads:
//   sA [m][k] stride 36 -> A-read bank = 4g + l4 (all distinct)
//   sW [k][n] stride 136 -> B-read bank = 8*l4 + g (all distinct)
template <int K_DIM>
__global__ void __launch_bounds__(256) mma_gemm_kernel(
    const float* __restrict__ A, const float* __restrict__ W,
    const float* __restrict__ rowscale, float* __restrict__ out, int n) {
    __shared__ uint32_t sA[128][36];
    __shared__ uint32_t sW[32][136];

    const int t = threadIdx.x;
    const int wid = t >> 5;
    const int lane = t & 31;
    const int g = lane >> 2;      // 0..7
    const int l4 = lane & 3;      // 0..3
    const int warpM = wid >> 2;   // 0..1
    const int warpN = wid & 3;    // 0..3
    const int row0 = blockIdx.x * 128;

    float acc[4][4][4];
#pragma unroll
    for (int mi = 0; mi < 4; mi++)
#pragma unroll
        for (int nj = 0; nj < 4; nj++)
#pragma unroll
            for (int r = 0; r < 4; r++) acc[mi][nj][r] = 0.f;

    for (int k0 = 0; k0 < K_DIM; k0 += 32) {
        // ---- stage A chunk: 128 rows x 32 k, convert to tf32 ----
#pragma unroll
        for (int i = 0; i < 4; i++) {
            int j4 = t + i * 256;              // 0..1023
            int r = j4 >> 3, kq = j4 & 7;
            int grow = row0 + r;
            float4 v = (grow < n)
                ? *reinterpret_cast<const float4*>(A + (size_t)grow * K_DIM + k0 + kq * 4)
                : make_float4(0.f, 0.f, 0.f, 0.f);
            uint4 b = make_uint4(f2tf32(v.x), f2tf32(v.y), f2tf32(v.z), f2tf32(v.w));
            *reinterpret_cast<uint4*>(&sA[r][kq * 4]) = b;
        }
        // ---- stage W chunk: 32 k x 128 n, convert to tf32 ----
#pragma unroll
        for (int i = 0; i < 4; i++) {
            int j4 = t + i * 256;              // 0..1023
            int kk = j4 >> 5, c4 = j4 & 31;
            float4 v = *reinterpret_cast<const float4*>(W + (size_t)(k0 + kk) * 128 + c4 * 4);
            uint4 b = make_uint4(f2tf32(v.x), f2tf32(v.y), f2tf32(v.z), f2tf32(v.w));
            *reinterpret_cast<uint4*>(&sW[kk][c4 * 4]) = b;
        }
        __syncthreads();
        // ---- 4 k8 steps ----
#pragma unroll
        for (int ks = 0; ks < 4; ks++) {
            const int k = ks * 8;
            uint32_t af[4][4], bf[4][2];
#pragma unroll
            for (int mi = 0; mi < 4; mi++) {
                int m = warpM * 64 + mi * 16 + g;
                af[mi][0] = sA[m][k + l4];
                af[mi][1] = sA[m + 8][k + l4];
                af[mi][2] = sA[m][k + l4 + 4];
                af[mi][3] = sA[m + 8][k + l4 + 4];
            }
#pragma unroll
            for (int nj = 0; nj < 4; nj++) {
                int nb = warpN * 32 + nj * 8 + g;
                bf[nj][0] = sW[k + l4][nb];
                bf[nj][1] = sW[k + l4 + 4][nb];
            }
#pragma unroll
            for (int mi = 0; mi < 4; mi++)
#pragma unroll
                for (int nj = 0; nj < 4; nj++)
                    mma_tf32(acc[mi][nj], af[mi], bf[nj]);
        }
        __syncthreads();
    }

    // ---- epilogue: scale rows, float2 stores ----
#pragma unroll
    for (int mi = 0; mi < 4; mi++) {
        int ra = row0 + warpM * 64 + mi * 16 + g;
        int rb = ra + 8;
        float sa = (ra < n) ? rowscale[ra] : 0.f;
        float sb = (rb < n) ? rowscale[rb] : 0.f;
#pragma unroll
        for (int nj = 0; nj < 4; nj++) {
            int col = warpN * 32 + nj * 8 + 2 * l4;
            if (ra < n) {
                float2 v = make_float2(acc[mi][nj][0] * sa, acc[mi][nj][1] * sa);
                *reinterpret_cast<float2*>(out + (size_t)ra * 128 + col) = v;
            }
            if (rb < n) {
                float2 v = make_float2(acc[mi][nj][2] * sb, acc[mi][nj][3] * sb);
                *reinterpret_cast<float2*>(out + (size_t)rb * 128 + col) = v;
            }
        }
    }
}

// ---------------- zero ints ----------------
__global__ void zeroi_kernel(int* __restrict__ p, int n) {
    int i = blockIdx.x * blockDim.x + threadIdx.x;
    if (i < n) p[i] = 0;
}

// ---------------- degree histogram (int) ----------------
__global__ void deg_kernel(const int* __restrict__ src, const int* __restrict__ dst,
                           int* __restrict__ cs, int* __restrict__ cd, int e) {
    int i = blockIdx.x * blockDim.x + threadIdx.x;
    if (i < e) {
        atomicAdd(&cs[src[i]], 1);
        atomicAdd(&cd[dst[i]], 1);
    }
}

__global__ void norm_kernel(const int* __restrict__ cs, const int* __restrict__ cd,
                            float* __restrict__ ncs, float* __restrict__ ncd, int n) {
    int i = blockIdx.x * blockDim.x + threadIdx.x;
    if (i < n) {
        ncs[i] = rsqrtf(fmaxf((float)cs[i], 1.f));
        ncd[i] = rsqrtf(fmaxf((float)cd[i], 1.f));
    }
}

// ---------------- scan stage 1 ----------------
__global__ void __launch_bounds__(256) scan_local_kernel(
    const int* __restrict__ in, int* __restrict__ out, int* __restrict__ bsum, int n) {
    __shared__ int wsum[8];
    int t = threadIdx.x;
    int base = blockIdx.x * 1024 + t * 4;
    int v[4];
#pragma unroll
    for (int i = 0; i < 4; i++) v[i] = (base + i < n) ? in[base + i] : 0;
    int tsum = v[0] + v[1] + v[2] + v[3];
    int lane = t & 31, wid = t >> 5;
    int inc = tsum;
#pragma unroll
    for (int off = 1; off < 32; off <<= 1) {
        int tmp = __shfl_up_sync(0xffffffffu, inc, off);
        if (lane >= off) inc += tmp;
    }
    if (lane == 31) wsum[wid] = inc;
    __syncthreads();
    if (t < 8) {
        int ws = wsum[t];
#pragma unroll
        for (int off = 1; off < 8; off <<= 1) {
            int tmp = __shfl_up_sync(0xffu, ws, off);
            if (t >= off) ws += tmp;
        }
        wsum[t] = ws;
    }
    __syncthreads();
    int excl = inc - tsum + (wid > 0 ? wsum[wid - 1] : 0);
    int run = excl;
#pragma unroll
    for (int i = 0; i < 4; i++) {
        if (base + i < n) out[base + i] = run;
        run += v[i];
    }
    if (t == 255) bsum[blockIdx.x] = wsum[7];
}

// ---------------- scan stage 2 ----------------
__global__ void scan_bsum_kernel(int* __restrict__ bsum, int nb) {
    __shared__ int s[128];
    int t = threadIdx.x;
    int v = (t < nb) ? bsum[t] : 0;
    s[t] = v;
    __syncthreads();
    for (int off = 1; off < 128; off <<= 1) {
        int tmp = (t >= off) ? s[t - off] : 0;
        __syncthreads();
        s[t] += tmp;
        __syncthreads();
    }
    if (t < nb) bsum[t] = s[t] - v;
}

// ---------------- scan stage 3 ----------------
__global__ void scan_add_kernel(int* __restrict__ rowptr, int* __restrict__ pos,
                                const int* __restrict__ bsum, int n) {
    int i = blockIdx.x * blockDim.x + threadIdx.x;
    if (i < n) {
        int v = rowptr[i] + bsum[i >> 10];
        rowptr[i] = v;
        pos[i] = v;
    }
    if (i == 0) rowptr[n] = EE;
}

// ---------------- CSR bucket fill ----------------
__global__ void fill_kernel(const int* __restrict__ src, const int* __restrict__ dst,
                            int* __restrict__ pos, int* __restrict__ esrc, int e) {
    int i = blockIdx.x * blockDim.x + threadIdx.x;
    if (i < e) {
        int p = atomicAdd(&pos[dst[i]], 1);
        esrc[p] = src[i];
    }
}

// ---------------- atomic-free aggregation: out[d] = agg(h[srcs])*cdst[d] + b -------
template <bool RELU>
__global__ void __launch_bounds__(256) agg_kernel(
    const float* __restrict__ h, const int* __restrict__ esrc,
    const int* __restrict__ rowptr, const float* __restrict__ cdst,
    const float* __restrict__ bias, float* __restrict__ out, int n) {
    int g = blockIdx.x * blockDim.x + threadIdx.x;
    int w = g >> 5;
    int lane = g & 31;
    if (w >= n) return;
    int beg = rowptr[w];
    int end = rowptr[w + 1];
    float4 acc = make_float4(0.f, 0.f, 0.f, 0.f);
    int e = beg;
    for (; e + 4 <= end; e += 4) {
        int s0 = __ldg(&esrc[e]);
        int s1 = __ldg(&esrc[e + 1]);
        int s2 = __ldg(&esrc[e + 2]);
        int s3 = __ldg(&esrc[e + 3]);
        float4 v0 = *((const float4*)(h + (size_t)s0 * 128) + lane);
        float4 v1 = *((const float4*)(h + (size_t)s1 * 128) + lane);
        float4 v2 = *((const float4*)(h + (size_t)s2 * 128) + lane);
        float4 v3 = *((const float4*)(h + (size_t)s3 * 128) + lane);
        acc.x += (v0.x + v1.x) + (v2.x + v3.x);
        acc.y += (v0.y + v1.y) + (v2.y + v3.y);
        acc.z += (v0.z + v1.z) + (v2.z + v3.z);
        acc.w += (v0.w + v1.w) + (v2.w + v3.w);
    }
    for (; e < end; e++) {
        int s = __ldg(&esrc[e]);
        float4 v = *((const float4*)(h + (size_t)s * 128) + lane);
        acc.x += v.x; acc.y += v.y; acc.z += v.z; acc.w += v.w;
    }
    float c = cdst[w];
    float4 b = ((const float4*)bias)[lane];
    float4 r = make_float4(acc.x * c + b.x, acc.y * c + b.y,
                           acc.z * c + b.z, acc.w * c + b.w);
    if (RELU) {
        r.x = fmaxf(r.x, 0.f); r.y = fmaxf(r.y, 0.f);
        r.z = fmaxf(r.z, 0.f); r.w = fmaxf(r.w, 0.f);
    }
    ((float4*)out)[(size_t)w * 32 + lane] = r;
}

// ---------------- classifier: logits = relu(h) @ Wc + bc ---------------------------
// 320 threads: t -> (row = t/40, col = t%40); float4 on both operands.
__global__ void __launch_bounds__(320) classifier_kernel(
    const float* __restrict__ h, const float* __restrict__ Wc,
    const float* __restrict__ bc, float* __restrict__ out, int n) {
    __shared__ float Wt[NCLS][132];   // [c][k]
    __shared__ float4 hs4[8][33];     // [r][k4], relu-applied
    __shared__ float bs[NCLS];

    const int t = threadIdx.x;
    for (int j = t; j < 128 * NCLS; j += 320) {
        int k = j / NCLS, c = j % NCLS;
        Wt[c][k] = Wc[j];
    }
    if (t < NCLS) bs[t] = bc[t];

    const int row0 = blockIdx.x * 64;
    const int r = t / NCLS;       // 0..7
    const int c = t % NCLS;       // 0..39
    for (int rr0 = 0; rr0 < 64; rr0 += 8) {
        __syncthreads();
        if (t < 256) {
            int lr = t >> 5, k4 = t & 31;
            int grow = row0 + rr0 + lr;
            float4 v = make_float4(0.f, 0.f, 0.f, 0.f);
            if (grow < n) {
                v = *reinterpret_cast<const float4*>(h + (size_t)grow * 128 + k4 * 4);
                v.x = fmaxf(v.x, 0.f); v.y = fmaxf(v.y, 0.f);
                v.z = fmaxf(v.z, 0.f); v.w = fmaxf(v.w, 0.f);
            }
            hs4[lr][k4] = v;
        }
        __syncthreads();
        float acc = bs[c];
#pragma unroll
        for (int k4 = 0; k4 < 32; k4++) {
            float4 hv = hs4[r][k4];
            float4 wv = *reinterpret_cast<const float4*>(&Wt[c][k4 * 4]);
            acc = fmaf(hv.x, wv.x, acc);
            acc = fmaf(hv.y, wv.y, acc);
            acc = fmaf(hv.z, wv.z, acc);
            acc = fmaf(hv.w, wv.w, acc);
        }
        int grow = row0 + rr0 + r;
        if (grow < n) out[(size_t)grow * NCLS + c] = acc;
    }
}

// ---------------- launch ------------------------------------------------------------
extern "C" void kernel_launch(void* const* d_in, const int* in_sizes, int n_in,
                              void* d_out, int out_size) {
    const float* x   = (const float*)d_in[0];
    const int*   src = (const int*)d_in[1];
    const int*   dst = (const int*)d_in[2];
    const float* W0  = (const float*)d_in[3];
    const float* b0  = (const float*)d_in[4];
    const float* W1  = (const float*)d_in[5];
    const float* b1  = (const float*)d_in[6];
    const float* Wc  = (const float*)d_in[7];
    const float* bc  = (const float*)d_in[8];
    float* out = (float*)d_out;
    float* out_h = out;                          // [N,128]
    float* out_logits = out + (size_t)NN * HID;  // [N,40]

    float *pCsrc, *pCdst, *pA, *pB;
    int *pCntS, *pCntD, *pRow, *pPos, *pBsum, *pEsrc;
    cudaGetSymbolAddress((void**)&pCsrc, g_csrc);
    cudaGetSymbolAddress((void**)&pCdst, g_cdst);
    cudaGetSymbolAddress((void**)&pA, g_bufA);
    cudaGetSymbolAddress((void**)&pB, g_bufB);
    cudaGetSymbolAddress((void**)&pCntS, g_cnt_s);
    cudaGetSymbolAddress((void**)&pCntD, g_cnt_d);
    cudaGetSymbolAddress((void**)&pRow, g_rowptr);
    cudaGetSymbolAddress((void**)&pPos, g_pos);
    cudaGetSymbolAddress((void**)&pBsum, g_bsum);
    cudaGetSymbolAddress((void**)&pEsrc, g_esrc);

    const int TB = 256;

    // ---- degree norms + CSR build (once; shared by both layers) ----
    zeroi_kernel<<<(NN + TB - 1) / TB, TB>>>(pCntS, NN);
    zeroi_kernel<<<(NN + TB - 1) / TB, TB>>>(pCntD, NN);
    deg_kernel<<<(EE + TB - 1) / TB, TB>>>(src, dst, pCntS, pCntD, EE);
    norm_kernel<<<(NN + TB - 1) / TB, TB>>>(pCntS, pCntD, pCsrc, pCdst, NN);
    scan_local_kernel<<<NB_SCAN, 256>>>(pCntD, pRow, pBsum, NN);
    scan_bsum_kernel<<<1, 128>>>(pBsum, NB_SCAN);
    scan_add_kernel<<<(NN + TB - 1) / TB, TB>>>(pRow, pPos, pBsum, NN);
    fill_kernel<<<(EE + TB - 1) / TB, TB>>>(src, dst, pPos, pEsrc, EE);

    const int nmma = (NN + 127) / 128;       // 782
    const int nagg = (NN * 32 + TB - 1) / TB;
    const int ncls = (NN + 63) / 64;         // 1563

    // ---- layer 0: bufA = (x @ W0) * c_src; bufB = relu(agg(bufA)*c_dst + b0) ----
    mma_gemm_kernel<FIN><<<nmma, 256>>>(x, W0, pCsrc, pA, NN);
    agg_kernel<true><<<nagg, TB>>>(pA, pEsrc, pRow, pCdst, b0, pB, NN);

    // ---- layer 1: bufA = (bufB @ W1) * c_src; out_h = agg(bufA)*c_dst + b1 ----
    mma_gemm_kernel<HID><<<nmma, 256>>>(pB, W1, pCsrc, pA, NN);
    agg_kernel<false><<<nagg, TB>>>(pA, pEsrc, pRow, pCdst, b1, out_h, NN);

    // ---- logits = relu(h) @ Wc + bc ----
    classifier_kernel<<<ncls, 320>>>(out_h, Wc, bc, out_logits, NN);
}

// round 8
// speedup vs baseline: 2.5856x; 1.0410x over previous
#include <cuda_runtime.h>
#include <cuda_fp16.h>
#include <cstdint>

#define NN 100000
#define EE 1600000
#define FIN 256
#define HID 128
#define NCLS 40
#define NB_SCAN 98   // ceil(NN/1024)

// ---------------- scratch (device globals; no allocation allowed) ----------------
__device__ float  g_csrc[NN];
__device__ float  g_cdst[NN];
__device__ int    g_cnt_s[NN];
__device__ int    g_cnt_d[NN];
__device__ int    g_rowptr[NN + 1];
__device__ int    g_pos[NN];
__device__ int    g_bsum[128];
__device__ int    g_esrc[EE];
__device__ __half g_half[(size_t)NN * HID];   // fp16 h (gather-side representation)
__device__ float  g_bufB[(size_t)NN * HID];   // fp32 intermediate

// ---------------- mma.sync tf32 helpers (baseline PTX, compiles at compute_103) ---
__device__ __forceinline__ uint32_t f2tf32(float x) {
    uint32_t r;
    asm("cvt.rna.tf32.f32 %0, %1;" : "=r"(r) : "f"(x));
    return r;
}
__device__ __forceinline__ void mma_tf32(float* d, const uint32_t* a, const uint32_t* b) {
    asm volatile(
        "mma.sync.aligned.m16n8k8.row.col.f32.tf32.tf32.f32 "
        "{%0,%1,%2,%3}, {%4,%5,%6,%7}, {%8,%9}, {%0,%1,%2,%3};"
        : "+f"(d[0]), "+f"(d[1]), "+f"(d[2]), "+f"(d[3])
        : "r"(a[0]), "r"(a[1]), "r"(a[2]), "r"(a[3]), "r"(b[0]), "r"(b[1]));
}

// ============ HMMA tf32 GEMM: out[r][c] = (A[r][:] @ W[:][c]) * rowscale[r] ========
// CTA tile 128x128; 8 warps (2x4); warp tile 64x32; K chunked by 32.
// HALF_OUT: epilogue emits packed __half (for the L2-gather path).
template <int K_DIM, bool HALF_OUT>
__global__ void __launch_bounds__(256) mma_gemm_kernel(
    const float* __restrict__ A, const float* __restrict__ W,
    const float* __restrict__ rowscale, void* __restrict__ out_v, int n) {
    __shared__ uint32_t sA[128][36];
    __shared__ uint32_t sW[32][136];

    const int t = threadIdx.x;
    const int wid = t >> 5;
    const int lane = t & 31;
    const int g = lane >> 2;      // 0..7
    const int l4 = lane & 3;      // 0..3
    const int warpM = wid >> 2;   // 0..1
    const int warpN = wid & 3;    // 0..3
    const int row0 = blockIdx.x * 128;

    float acc[4][4][4];
#pragma unroll
    for (int mi = 0; mi < 4; mi++)
#pragma unroll
        for (int nj = 0; nj < 4; nj++)
#pragma unroll
            for (int r = 0; r < 4; r++) acc[mi][nj][r] = 0.f;

    for (int k0 = 0; k0 < K_DIM; k0 += 32) {
        // ---- stage A chunk: 128 rows x 32 k, convert to tf32 ----
#pragma unroll
        for (int i = 0; i < 4; i++) {
            int j4 = t + i * 256;              // 0..1023
            int r = j4 >> 3, kq = j4 & 7;
            int grow = row0 + r;
            float4 v = (grow < n)
                ? *reinterpret_cast<const float4*>(A + (size_t)grow * K_DIM + k0 + kq * 4)
                : make_float4(0.f, 0.f, 0.f, 0.f);
            uint4 b = make_uint4(f2tf32(v.x), f2tf32(v.y), f2tf32(v.z), f2tf32(v.w));
            *reinterpret_cast<uint4*>(&sA[r][kq * 4]) = b;
        }
        // ---- stage W chunk: 32 k x 128 n, convert to tf32 ----
#pragma unroll
        for (int i = 0; i < 4; i++) {
            int j4 = t + i * 256;              // 0..1023
            int kk = j4 >> 5, c4 = j4 & 31;
            float4 v = *reinterpret_cast<const float4*>(W + (size_t)(k0 + kk) * 128 + c4 * 4);
            uint4 b = make_uint4(f2tf32(v.x), f2tf32(v.y), f2tf32(v.z), f2tf32(v.w));
            *reinterpret_cast<uint4*>(&sW[kk][c4 * 4]) = b;
        }
        __syncthreads();
        // ---- 4 k8 steps ----
#pragma unroll
        for (int ks = 0; ks < 4; ks++) {
            const int k = ks * 8;
            uint32_t af[4][4], bf[4][2];
#pragma unroll
            for (int mi = 0; mi < 4; mi++) {
                int m = warpM * 64 + mi * 16 + g;
                af[mi][0] = sA[m][k + l4];
                af[mi][1] = sA[m + 8][k + l4];
                af[mi][2] = sA[m][k + l4 + 4];
                af[mi][3] = sA[m + 8][k + l4 + 4];
            }
#pragma unroll
            for (int nj = 0; nj < 4; nj++) {
                int nb = warpN * 32 + nj * 8 + g;
                bf[nj][0] = sW[k + l4][nb];
                bf[nj][1] = sW[k + l4 + 4][nb];
            }
#pragma unroll
            for (int mi = 0; mi < 4; mi++)
#pragma unroll
                for (int nj = 0; nj < 4; nj++)
                    mma_tf32(acc[mi][nj], af[mi], bf[nj]);
        }
        __syncthreads();
    }

    // ---- epilogue: scale rows, store (fp16 or fp32) ----
#pragma unroll
    for (int mi = 0; mi < 4; mi++) {
        int ra = row0 + warpM * 64 + mi * 16 + g;
        int rb = ra + 8;
        float sa = (ra < n) ? rowscale[ra] : 0.f;
        float sb = (rb < n) ? rowscale[rb] : 0.f;
#pragma unroll
        for (int nj = 0; nj < 4; nj++) {
            int col = warpN * 32 + nj * 8 + 2 * l4;
            if (HALF_OUT) {
                __half* o = (__half*)out_v;
                if (ra < n)
                    *reinterpret_cast<__half2*>(o + (size_t)ra * 128 + col) =
                        __floats2half2_rn(acc[mi][nj][0] * sa, acc[mi][nj][1] * sa);
                if (rb < n)
                    *reinterpret_cast<__half2*>(o + (size_t)rb * 128 + col) =
                        __floats2half2_rn(acc[mi][nj][2] * sb, acc[mi][nj][3] * sb);
            } else {
                float* o = (float*)out_v;
                if (ra < n) {
                    float2 v = make_float2(acc[mi][nj][0] * sa, acc[mi][nj][1] * sa);
                    *reinterpret_cast<float2*>(o + (size_t)ra * 128 + col) = v;
                }
                if (rb < n) {
                    float2 v = make_float2(acc[mi][nj][2] * sb, acc[mi][nj][3] * sb);
                    *reinterpret_cast<float2*>(o + (size_t)rb * 128 + col) = v;
                }
            }
        }
    }
}

// ---------------- zero ints ----------------
__global__ void zeroi_kernel(int* __restrict__ p, int n) {
    int i = blockIdx.x * blockDim.x + threadIdx.x;
    if (i < n) p[i] = 0;
}

// ---------------- degree histogram (int) ----------------
__global__ void deg_kernel(const int* __restrict__ src, const int* __restrict__ dst,
                           int* __restrict__ cs, int* __restrict__ cd, int e) {
    int i = blockIdx.x * blockDim.x + threadIdx.x;
    if (i < e) {
        atomicAdd(&cs[src[i]], 1);
        atomicAdd(&cd[dst[i]], 1);
    }
}

__global__ void norm_kernel(const int* __restrict__ cs, const int* __restrict__ cd,
                            float* __restrict__ ncs, float* __restrict__ ncd, int n) {
    int i = blockIdx.x * blockDim.x + threadIdx.x;
    if (i < n) {
        ncs[i] = rsqrtf(fmaxf((float)cs[i], 1.f));
        ncd[i] = rsqrtf(fmaxf((float)cd[i], 1.f));
    }
}

// ---------------- scan stage 1 ----------------
__global__ void __launch_bounds__(256) scan_local_kernel(
    const int* __restrict__ in, int* __restrict__ out, int* __restrict__ bsum, int n) {
    __shared__ int wsum[8];
    int t = threadIdx.x;
    int base = blockIdx.x * 1024 + t * 4;
    int v[4];
#pragma unroll
    for (int i = 0; i < 4; i++) v[i] = (base + i < n) ? in[base + i] : 0;
    int tsum = v[0] + v[1] + v[2] + v[3];
    int lane = t & 31, wid = t >> 5;
    int inc = tsum;
#pragma unroll
    for (int off = 1; off < 32; off <<= 1) {
        int tmp = __shfl_up_sync(0xffffffffu, inc, off);
        if (lane >= off) inc += tmp;
    }
    if (lane == 31) wsum[wid] = inc;
    __syncthreads();
    if (t < 8) {
        int ws = wsum[t];
#pragma unroll
        for (int off = 1; off < 8; off <<= 1) {
            int tmp = __shfl_up_sync(0xffu, ws, off);
            if (t >= off) ws += tmp;
        }
        wsum[t] = ws;
    }
    __syncthreads();
    int excl = inc - tsum + (wid > 0 ? wsum[wid - 1] : 0);
    int run = excl;
#pragma unroll
    for (int i = 0; i < 4; i++) {
        if (base + i < n) out[base + i] = run;
        run += v[i];
    }
    if (t == 255) bsum[blockIdx.x] = wsum[7];
}

// ---------------- scan stage 2 ----------------
__global__ void scan_bsum_kernel(int* __restrict__ bsum, int nb) {
    __shared__ int s[128];
    int t = threadIdx.x;
    int v = (t < nb) ? bsum[t] : 0;
    s[t] = v;
    __syncthreads();
    for (int off = 1; off < 128; off <<= 1) {
        int tmp = (t >= off) ? s[t - off] : 0;
        __syncthreads();
        s[t] += tmp;
        __syncthreads();
    }
    if (t < nb) bsum[t] = s[t] - v;
}

// ---------------- scan stage 3 ----------------
__global__ void scan_add_kernel(int* __restrict__ rowptr, int* __restrict__ pos,
                                const int* __restrict__ bsum, int n) {
    int i = blockIdx.x * blockDim.x + threadIdx.x;
    if (i < n) {
        int v = rowptr[i] + bsum[i >> 10];
        rowptr[i] = v;
        pos[i] = v;
    }
    if (i == 0) rowptr[n] = EE;
}

// ---------------- CSR bucket fill ----------------
__global__ void fill_kernel(const int* __restrict__ src, const int* __restrict__ dst,
                            int* __restrict__ pos, int* __restrict__ esrc, int e) {
    int i = blockIdx.x * blockDim.x + threadIdx.x;
    if (i < e) {
        int p = atomicAdd(&pos[dst[i]], 1);
        esrc[p] = src[i];
    }
}

// ------- atomic-free aggregation (fp16 gather): out[d] = (sum h16[srcs])*cdst + b ---
// warp per dst; lane gathers int2 = 4 halfs; accumulate fp32; fp32 output.
template <bool RELU>
__global__ void __launch_bounds__(256) agg_half_kernel(
    const __half* __restrict__ h, const int* __restrict__ esrc,
    const int* __restrict__ rowptr, const float* __restrict__ cdst,
    const float* __restrict__ bias, float* __restrict__ out, int n) {
    int g = blockIdx.x * blockDim.x + threadIdx.x;
    int w = g >> 5;
    int lane = g & 31;
    if (w >= n) return;
    int beg = rowptr[w];
    int end = rowptr[w + 1];
    const int2* hb = reinterpret_cast<const int2*>(h);  // 1 int2 = 4 halfs; 32/row
    float4 acc = make_float4(0.f, 0.f, 0.f, 0.f);
    int e = beg;
    for (; e + 4 <= end; e += 4) {
        int s0 = __ldg(&esrc[e]);
        int s1 = __ldg(&esrc[e + 1]);
        int s2 = __ldg(&esrc[e + 2]);
        int s3 = __ldg(&esrc[e + 3]);
        int2 r0 = __ldg(&hb[(size_t)s0 * 32 + lane]);
        int2 r1 = __ldg(&hb[(size_t)s1 * 32 + lane]);
        int2 r2 = __ldg(&hb[(size_t)s2 * 32 + lane]);
        int2 r3 = __ldg(&hb[(size_t)s3 * 32 + lane]);
        float2 a0 = __half22float2(*reinterpret_cast<__half2*>(&r0.x));
        float2 b0 = __half22float2(*reinterpret_cast<__half2*>(&r0.y));
        float2 a1 = __half22float2(*reinterpret_cast<__half2*>(&r1.x));
        float2 b1 = __half22float2(*reinterpret_cast<__half2*>(&r1.y));
        float2 a2 = __half22float2(*reinterpret_cast<__half2*>(&r2.x));
        float2 b2 = __half22float2(*reinterpret_cast<__half2*>(&r2.y));
        float2 a3 = __half22float2(*reinterpret_cast<__half2*>(&r3.x));
        float2 b3 = __half22float2(*reinterpret_cast<__half2*>(&r3.y));
        acc.x += (a0.x + a1.x) + (a2.x + a3.x);
        acc.y += (a0.y + a1.y) + (a2.y + a3.y);
        acc.z += (b0.x + b1.x) + (b2.x + b3.x);
        acc.w += (b0.y + b1.y) + (b2.y + b3.y);
    }
    for (; e < end; e++) {
        int s = __ldg(&esrc[e]);
        int2 r0 = __ldg(&hb[(size_t)s * 32 + lane]);
        float2 a0 = __half22float2(*reinterpret_cast<__half2*>(&r0.x));
        float2 b0 = __half22float2(*reinterpret_cast<__half2*>(&r0.y));
        acc.x += a0.x; acc.y += a0.y; acc.z += b0.x; acc.w += b0.y;
    }
    float c = cdst[w];
    float4 b = ((const float4*)bias)[lane];
    float4 r = make_float4(acc.x * c + b.x, acc.y * c + b.y,
                           acc.z * c + b.z, acc.w * c + b.w);
    if (RELU) {
        r.x = fmaxf(r.x, 0.f); r.y = fmaxf(r.y, 0.f);
        r.z = fmaxf(r.z, 0.f); r.w = fmaxf(r.w, 0.f);
    }
    ((float4*)out)[(size_t)w * 32 + lane] = r;
}

// ---------------- classifier: logits = relu(h) @ Wc + bc ---------------------------
// 320 threads: t -> (row = t/40, col = t%40); float4 on both operands.
__global__ void __launch_bounds__(320) classifier_kernel(
    const float* __restrict__ h, const float* __restrict__ Wc,
    const float* __restrict__ bc, float* __restrict__ out, int n) {
    __shared__ float Wt[NCLS][132];   // [c][k]
    __shared__ float4 hs4[8][33];     // [r][k4], relu-applied
    __shared__ float bs[NCLS];

    const int t = threadIdx.x;
    for (int j = t; j < 128 * NCLS; j += 320) {
        int k = j / NCLS, c = j % NCLS;
        Wt[c][k] = Wc[j];
    }
    if (t < NCLS) bs[t] = bc[t];

    const int row0 = blockIdx.x * 64;
    const int r = t / NCLS;       // 0..7
    const int c = t % NCLS;       // 0..39
    for (int rr0 = 0; rr0 < 64; rr0 += 8) {
        __syncthreads();
        if (t < 256) {
            int lr = t >> 5, k4 = t & 31;
            int grow = row0 + rr0 + lr;
            float4 v = make_float4(0.f, 0.f, 0.f, 0.f);
            if (grow < n) {
                v = *reinterpret_cast<const float4*>(h + (size_t)grow * 128 + k4 * 4);
                v.x = fmaxf(v.x, 0.f); v.y = fmaxf(v.y, 0.f);
                v.z = fmaxf(v.z, 0.f); v.w = fmaxf(v.w, 0.f);
            }
            hs4[lr][k4] = v;
        }
        __syncthreads();
        float acc = bs[c];
#pragma unroll
        for (int k4 = 0; k4 < 32; k4++) {
            float4 hv = hs4[r][k4];
            float4 wv = *reinterpret_cast<const float4*>(&Wt[c][k4 * 4]);
            acc = fmaf(hv.x, wv.x, acc);
            acc = fmaf(hv.y, wv.y, acc);
            acc = fmaf(hv.z, wv.z, acc);
            acc = fmaf(hv.w, wv.w, acc);
        }
        int grow = row0 + rr0 + r;
        if (grow < n) out[(size_t)grow * NCLS + c] = acc;
    }
}

// ---------------- launch ------------------------------------------------------------
extern "C" void kernel_launch(void* const* d_in, const int* in_sizes, int n_in,
                              void* d_out, int out_size) {
    const float* x   = (const float*)d_in[0];
    const int*   src = (const int*)d_in[1];
    const int*   dst = (const int*)d_in[2];
    const float* W0  = (const float*)d_in[3];
    const float* b0  = (const float*)d_in[4];
    const float* W1  = (const float*)d_in[5];
    const float* b1  = (const float*)d_in[6];
    const float* Wc  = (const float*)d_in[7];
    const float* bc  = (const float*)d_in[8];
    float* out = (float*)d_out;
    float* out_h = out;                          // [N,128]
    float* out_logits = out + (size_t)NN * HID;  // [N,40]

    float *pCsrc, *pCdst, *pB;
    __half* pH;
    int *pCntS, *pCntD, *pRow, *pPos, *pBsum, *pEsrc;
    cudaGetSymbolAddress((void**)&pCsrc, g_csrc);
    cudaGetSymbolAddress((void**)&pCdst, g_cdst);
    cudaGetSymbolAddress((void**)&pH, g_half);
    cudaGetSymbolAddress((void**)&pB, g_bufB);
    cudaGetSymbolAddress((void**)&pCntS, g_cnt_s);
    cudaGetSymbolAddress((void**)&pCntD, g_cnt_d);
    cudaGetSymbolAddress((void**)&pRow, g_rowptr);
    cudaGetSymbolAddress((void**)&pPos, g_pos);
    cudaGetSymbolAddress((void**)&pBsum, g_bsum);
    cudaGetSymbolAddress((void**)&pEsrc, g_esrc);

    const int TB = 256;

    // ---- degree norms + CSR build (once; shared by both layers) ----
    zeroi_kernel<<<(NN + TB - 1) / TB, TB>>>(pCntS, NN);
    zeroi_kernel<<<(NN + TB - 1) / TB, TB>>>(pCntD, NN);
    deg_kernel<<<(EE + TB - 1) / TB, TB>>>(src, dst, pCntS, pCntD, EE);
    norm_kernel<<<(NN + TB - 1) / TB, TB>>>(pCntS, pCntD, pCsrc, pCdst, NN);
    scan_local_kernel<<<NB_SCAN, 256>>>(pCntD, pRow, pBsum, NN);
    scan_bsum_kernel<<<1, 128>>>(pBsum, NB_SCAN);
    scan_add_kernel<<<(NN + TB - 1) / TB, TB>>>(pRow, pPos, pBsum, NN);
    fill_kernel<<<(EE + TB - 1) / TB, TB>>>(src, dst, pPos, pEsrc, EE);

    const int nmma = (NN + 127) / 128;       // 782
    const int nagg = (NN * 32 + TB - 1) / TB;
    const int ncls = (NN + 63) / 64;         // 1563

    // ---- layer 0: h16 = (x @ W0)*c_src; bufB = relu(agg(h16)*c_dst + b0) ----
    mma_gemm_kernel<FIN, true><<<nmma, 256>>>(x, W0, pCsrc, pH, NN);
    agg_half_kernel<true><<<nagg, TB>>>(pH, pEsrc, pRow, pCdst, b0, pB, NN);

    // ---- layer 1: h16 = (bufB @ W1)*c_src; out_h = agg(h16)*c_dst + b1 ----
    mma_gemm_kernel<HID, true><<<nmma, 256>>>(pB, W1, pCsrc, pH, NN);
    agg_half_kernel<false><<<nagg, TB>>>(pH, pEsrc, pRow, pCdst, b1, out_h, NN);

    // ---- logits = relu(h) @ Wc + bc ----
    classifier_kernel<<<ncls, 320>>>(out_h, Wc, bc, out_logits, NN);
}

// round 9
// speedup vs baseline: 2.6066x; 1.0081x over previous
#include <cuda_runtime.h>
#include <cuda_fp16.h>
#include <cstdint>

#define NN 100000
#define EE 1600000
#define FIN 256
#define HID 128
#define NCLS 40
#define NB_SCAN 98   // ceil(NN/1024)

// ---------------- scratch (device globals; no allocation allowed) ----------------
__device__ float  g_csrc[NN];
__device__ float  g_cdst[NN];
__device__ int    g_cnt_s[NN];
__device__ int    g_cnt_d[NN];
__device__ int    g_rowptr[NN + 1];
__device__ int    g_pos[NN];
__device__ int    g_bsum[128];
__device__ int    g_esrc[EE];
__device__ __half g_half[(size_t)NN * HID];   // fp16 h (gather-side representation)
__device__ float  g_bufB[(size_t)NN * HID];   // fp32 intermediate

// ---------------- mma.sync tf32 helpers (baseline PTX, compiles at compute_103) ---
__device__ __forceinline__ uint32_t f2tf32(float x) {
    uint32_t r;
    asm("cvt.rna.tf32.f32 %0, %1;" : "=r"(r) : "f"(x));
    return r;
}
__device__ __forceinline__ void mma_tf32(float* d, const uint32_t* a, const uint32_t* b) {
    asm volatile(
        "mma.sync.aligned.m16n8k8.row.col.f32.tf32.tf32.f32 "
        "{%0,%1,%2,%3}, {%4,%5,%6,%7}, {%8,%9}, {%0,%1,%2,%3};"
        : "+f"(d[0]), "+f"(d[1]), "+f"(d[2]), "+f"(d[3])
        : "r"(a[0]), "r"(a[1]), "r"(a[2]), "r"(a[3]), "r"(b[0]), "r"(b[1]));
}

// ============ HMMA tf32 GEMM: out[r][c] = (A[r][:] @ W[:][c]) * rowscale[r] ========
// CTA tile 128x128; 8 warps (2x4); warp tile 64x32; K chunked by 32.
// HALF_OUT: epilogue emits packed __half (for the L2-gather path).
template <int K_DIM, bool HALF_OUT>
__global__ void __launch_bounds__(256) mma_gemm_kernel(
    const float* __restrict__ A, const float* __restrict__ W,
    const float* __restrict__ rowscale, void* __restrict__ out_v, int n) {
    __shared__ uint32_t sA[128][36];
    __shared__ uint32_t sW[32][136];

    const int t = threadIdx.x;
    const int wid = t >> 5;
    const int lane = t & 31;
    const int g = lane >> 2;      // 0..7
    const int l4 = lane & 3;      // 0..3
    const int warpM = wid >> 2;   // 0..1
    const int warpN = wid & 3;    // 0..3
    const int row0 = blockIdx.x * 128;

    float acc[4][4][4];
#pragma unroll
    for (int mi = 0; mi < 4; mi++)
#pragma unroll
        for (int nj = 0; nj < 4; nj++)
#pragma unroll
            for (int r = 0; r < 4; r++) acc[mi][nj][r] = 0.f;

    for (int k0 = 0; k0 < K_DIM; k0 += 32) {
        // ---- stage A chunk: 128 rows x 32 k, convert to tf32 ----
#pragma unroll
        for (int i = 0; i < 4; i++) {
            int j4 = t + i * 256;              // 0..1023
            int r = j4 >> 3, kq = j4 & 7;
            int grow = row0 + r;
            float4 v = (grow < n)
                ? *reinterpret_cast<const float4*>(A + (size_t)grow * K_DIM + k0 + kq * 4)
                : make_float4(0.f, 0.f, 0.f, 0.f);
            uint4 b = make_uint4(f2tf32(v.x), f2tf32(v.y), f2tf32(v.z), f2tf32(v.w));
            *reinterpret_cast<uint4*>(&sA[r][kq * 4]) = b;
        }
        // ---- stage W chunk: 32 k x 128 n, convert to tf32 ----
#pragma unroll
        for (int i = 0; i < 4; i++) {
            int j4 = t + i * 256;              // 0..1023
            int kk = j4 >> 5, c4 = j4 & 31;
            float4 v = *reinterpret_cast<const float4*>(W + (size_t)(k0 + kk) * 128 + c4 * 4);
            uint4 b = make_uint4(f2tf32(v.x), f2tf32(v.y), f2tf32(v.z), f2tf32(v.w));
            *reinterpret_cast<uint4*>(&sW[kk][c4 * 4]) = b;
        }
        __syncthreads();
        // ---- 4 k8 steps ----
#pragma unroll
        for (int ks = 0; ks < 4; ks++) {
            const int k = ks * 8;
            uint32_t af[4][4], bf[4][2];
#pragma unroll
            for (int mi = 0; mi < 4; mi++) {
                int m = warpM * 64 + mi * 16 + g;
                af[mi][0] = sA[m][k + l4];
                af[mi][1] = sA[m + 8][k + l4];
                af[mi][2] = sA[m][k + l4 + 4];
                af[mi][3] = sA[m + 8][k + l4 + 4];
            }
#pragma unroll
            for (int nj = 0; nj < 4; nj++) {
                int nb = warpN * 32 + nj * 8 + g;
                bf[nj][0] = sW[k + l4][nb];
                bf[nj][1] = sW[k + l4 + 4][nb];
            }
#pragma unroll
            for (int mi = 0; mi < 4; mi++)
#pragma unroll
                for (int nj = 0; nj < 4; nj++)
                    mma_tf32(acc[mi][nj], af[mi], bf[nj]);
        }
        __syncthreads();
    }

    // ---- epilogue: scale rows, store (fp16 or fp32) ----
#pragma unroll
    for (int mi = 0; mi < 4; mi++) {
        int ra = row0 + warpM * 64 + mi * 16 + g;
        int rb = ra + 8;
        float sa = (ra < n) ? rowscale[ra] : 0.f;
        float sb = (rb < n) ? rowscale[rb] : 0.f;
#pragma unroll
        for (int nj = 0; nj < 4; nj++) {
            int col = warpN * 32 + nj * 8 + 2 * l4;
            if (HALF_OUT) {
                __half* o = (__half*)out_v;
                if (ra < n)
                    *reinterpret_cast<__half2*>(o + (size_t)ra * 128 + col) =
                        __floats2half2_rn(acc[mi][nj][0] * sa, acc[mi][nj][1] * sa);
                if (rb < n)
                    *reinterpret_cast<__half2*>(o + (size_t)rb * 128 + col) =
                        __floats2half2_rn(acc[mi][nj][2] * sb, acc[mi][nj][3] * sb);
            } else {
                float* o = (float*)out_v;
                if (ra < n) {
                    float2 v = make_float2(acc[mi][nj][0] * sa, acc[mi][nj][1] * sa);
                    *reinterpret_cast<float2*>(o + (size_t)ra * 128 + col) = v;
                }
                if (rb < n) {
                    float2 v = make_float2(acc[mi][nj][2] * sb, acc[mi][nj][3] * sb);
                    *reinterpret_cast<float2*>(o + (size_t)rb * 128 + col) = v;
                }
            }
        }
    }
}

// ---------------- zero ints ----------------
__global__ void zeroi_kernel(int* __restrict__ p, int n) {
    int i = blockIdx.x * blockDim.x + threadIdx.x;
    if (i < n) p[i] = 0;
}

// ---------------- degree histogram (int) ----------------
__global__ void deg_kernel(const int* __restrict__ src, const int* __restrict__ dst,
                           int* __restrict__ cs, int* __restrict__ cd, int e) {
    int i = blockIdx.x * blockDim.x + threadIdx.x;
    if (i < e) {
        atomicAdd(&cs[src[i]], 1);
        atomicAdd(&cd[dst[i]], 1);
    }
}

__global__ void norm_kernel(const int* __restrict__ cs, const int* __restrict__ cd,
                            float* __restrict__ ncs, float* __restrict__ ncd, int n) {
    int i = blockIdx.x * blockDim.x + threadIdx.x;
    if (i < n) {
        ncs[i] = rsqrtf(fmaxf((float)cs[i], 1.f));
        ncd[i] = rsqrtf(fmaxf((float)cd[i], 1.f));
    }
}

// ---------------- scan stage 1 ----------------
__global__ void __launch_bounds__(256) scan_local_kernel(
    const int* __restrict__ in, int* __restrict__ out, int* __restrict__ bsum, int n) {
    __shared__ int wsum[8];
    int t = threadIdx.x;
    int base = blockIdx.x * 1024 + t * 4;
    int v[4];
#pragma unroll
    for (int i = 0; i < 4; i++) v[i] = (base + i < n) ? in[base + i] : 0;
    int tsum = v[0] + v[1] + v[2] + v[3];
    int lane = t & 31, wid = t >> 5;
    int inc = tsum;
#pragma unroll
    for (int off = 1; off < 32; off <<= 1) {
        int tmp = __shfl_up_sync(0xffffffffu, inc, off);
        if (lane >= off) inc += tmp;
    }
    if (lane == 31) wsum[wid] = inc;
    __syncthreads();
    if (t < 8) {
        int ws = wsum[t];
#pragma unroll
        for (int off = 1; off < 8; off <<= 1) {
            int tmp = __shfl_up_sync(0xffu, ws, off);
            if (t >= off) ws += tmp;
        }
        wsum[t] = ws;
    }
    __syncthreads();
    int excl = inc - tsum + (wid > 0 ? wsum[wid - 1] : 0);
    int run = excl;
#pragma unroll
    for (int i = 0; i < 4; i++) {
        if (base + i < n) out[base + i] = run;
        run += v[i];
    }
    if (t == 255) bsum[blockIdx.x] = wsum[7];
}

// ---------------- scan stage 2 ----------------
__global__ void scan_bsum_kernel(int* __restrict__ bsum, int nb) {
    __shared__ int s[128];
    int t = threadIdx.x;
    int v = (t < nb) ? bsum[t] : 0;
    s[t] = v;
    __syncthreads();
    for (int off = 1; off < 128; off <<= 1) {
        int tmp = (t >= off) ? s[t - off] : 0;
        __syncthreads();
        s[t] += tmp;
        __syncthreads();
    }
    if (t < nb) bsum[t] = s[t] - v;
}

// ---------------- scan stage 3 ----------------
__global__ void scan_add_kernel(int* __restrict__ rowptr, int* __restrict__ pos,
                                const int* __restrict__ bsum, int n) {
    int i = blockIdx.x * blockDim.x + threadIdx.x;
    if (i < n) {
        int v = rowptr[i] + bsum[i >> 10];
        rowptr[i] = v;
        pos[i] = v;
    }
    if (i == 0) rowptr[n] = EE;
}

// ---------------- CSR bucket fill ----------------
__global__ void fill_kernel(const int* __restrict__ src, const int* __restrict__ dst,
                            int* __restrict__ pos, int* __restrict__ esrc, int e) {
    int i = blockIdx.x * blockDim.x + threadIdx.x;
    if (i < e) {
        int p = atomicAdd(&pos[dst[i]], 1);
        esrc[p] = src[i];
    }
}

// ------- atomic-free aggregation (fp16 gather): out[d] = (sum h16[srcs])*cdst + b ---
// warp per dst; lane gathers int2 = 4 halfs; accumulate fp32; fp32 output.
template <bool RELU>
__global__ void __launch_bounds__(256) agg_half_kernel(
    const __half* __restrict__ h, const int* __restrict__ esrc,
    const int* __restrict__ rowptr, const float* __restrict__ cdst,
    const float* __restrict__ bias, float* __restrict__ out, int n) {
    int g = blockIdx.x * blockDim.x + threadIdx.x;
    int w = g >> 5;
    int lane = g & 31;
    if (w >= n) return;
    int beg = rowptr[w];
    int end = rowptr[w + 1];
    const int2* hb = reinterpret_cast<const int2*>(h);  // 1 int2 = 4 halfs; 32/row
    float4 acc = make_float4(0.f, 0.f, 0.f, 0.f);
    int e = beg;
    for (; e + 4 <= end; e += 4) {
        int s0 = __ldg(&esrc[e]);
        int s1 = __ldg(&esrc[e + 1]);
        int s2 = __ldg(&esrc[e + 2]);
        int s3 = __ldg(&esrc[e + 3]);
        int2 r0 = __ldg(&hb[(size_t)s0 * 32 + lane]);
        int2 r1 = __ldg(&hb[(size_t)s1 * 32 + lane]);
        int2 r2 = __ldg(&hb[(size_t)s2 * 32 + lane]);
        int2 r3 = __ldg(&hb[(size_t)s3 * 32 + lane]);
        float2 a0 = __half22float2(*reinterpret_cast<__half2*>(&r0.x));
        float2 b0 = __half22float2(*reinterpret_cast<__half2*>(&r0.y));
        float2 a1 = __half22float2(*reinterpret_cast<__half2*>(&r1.x));
        float2 b1 = __half22float2(*reinterpret_cast<__half2*>(&r1.y));
        float2 a2 = __half22float2(*reinterpret_cast<__half2*>(&r2.x));
        float2 b2 = __half22float2(*reinterpret_cast<__half2*>(&r2.y));
        float2 a3 = __half22float2(*reinterpret_cast<__half2*>(&r3.x));
        float2 b3 = __half22float2(*reinterpret_cast<__half2*>(&r3.y));
        acc.x += (a0.x + a1.x) + (a2.x + a3.x);
        acc.y += (a0.y + a1.y) + (a2.y + a3.y);
        acc.z += (b0.x + b1.x) + (b2.x + b3.x);
        acc.w += (b0.y + b1.y) + (b2.y + b3.y);
    }
    for (; e < end; e++) {
        int s = __ldg(&esrc[e]);
        int2 r0 = __ldg(&hb[(size_t)s * 32 + lane]);
        float2 a0 = __half22float2(*reinterpret_cast<__half2*>(&r0.x));
        float2 b0 = __half22float2(*reinterpret_cast<__half2*>(&r0.y));
        acc.x += a0.x; acc.y += a0.y; acc.z += b0.x; acc.w += b0.y;
    }
    float c = cdst[w];
    float4 b = ((const float4*)bias)[lane];
    float4 r = make_float4(acc.x * c + b.x, acc.y * c + b.y,
                           acc.z * c + b.z, acc.w * c + b.w);
    if (RELU) {
        r.x = fmaxf(r.x, 0.f); r.y = fmaxf(r.y, 0.f);
        r.z = fmaxf(r.z, 0.f); r.w = fmaxf(r.w, 0.f);
    }
    ((float4*)out)[(size_t)w * 32 + lane] = r;
}

// ---------------- classifier: logits = relu(h) @ Wc + bc ---------------------------
// 320 threads: t -> (row = t/40, col = t%40); float4 on both operands.
__global__ void __launch_bounds__(320) classifier_kernel(
    const float* __restrict__ h, const float* __restrict__ Wc,
    const float* __restrict__ bc, float* __restrict__ out, int n) {
    __shared__ float Wt[NCLS][132];   // [c][k]
    __shared__ float4 hs4[8][33];     // [r][k4], relu-applied
    __shared__ float bs[NCLS];

    const int t = threadIdx.x;
    for (int j = t; j < 128 * NCLS; j += 320) {
        int k = j / NCLS, c = j % NCLS;
        Wt[c][k] = Wc[j];
    }
    if (t < NCLS) bs[t] = bc[t];

    const int row0 = blockIdx.x * 64;
    const int r = t / NCLS;       // 0..7
    const int c = t % NCLS;       // 0..39
    for (int rr0 = 0; rr0 < 64; rr0 += 8) {
        __syncthreads();
        if (t < 256) {
            int lr = t >> 5, k4 = t & 31;
            int grow = row0 + rr0 + lr;
            float4 v = make_float4(0.f, 0.f, 0.f, 0.f);
            if (grow < n) {
                v = *reinterpret_cast<const float4*>(h + (size_t)grow * 128 + k4 * 4);
                v.x = fmaxf(v.x, 0.f); v.y = fmaxf(v.y, 0.f);
                v.z = fmaxf(v.z, 0.f); v.w = fmaxf(v.w, 0.f);
            }
            hs4[lr][k4] = v;
        }
        __syncthreads();
        float acc = bs[c];
#pragma unroll
        for (int k4 = 0; k4 < 32; k4++) {
            float4 hv = hs4[r][k4];
            float4 wv = *reinterpret_cast<const float4*>(&Wt[c][k4 * 4]);
            acc = fmaf(hv.x, wv.x, acc);
            acc = fmaf(hv.y, wv.y, acc);
            acc = fmaf(hv.z, wv.z, acc);
            acc = fmaf(hv.w, wv.w, acc);
        }
        int grow = row0 + rr0 + r;
        if (grow < n) out[(size_t)grow * NCLS + c] = acc;
    }
}

// ---------------- launch ------------------------------------------------------------
extern "C" void kernel_launch(void* const* d_in, const int* in_sizes, int n_in,
                              void* d_out, int out_size) {
    const float* x   = (const float*)d_in[0];
    const int*   src = (const int*)d_in[1];
    const int*   dst = (const int*)d_in[2];
    const float* W0  = (const float*)d_in[3];
    const float* b0  = (const float*)d_in[4];
    const float* W1  = (const float*)d_in[5];
    const float* b1  = (const float*)d_in[6];
    const float* Wc  = (const float*)d_in[7];
    const float* bc  = (const float*)d_in[8];
    float* out = (float*)d_out;
    float* out_h = out;                          // [N,128]
    float* out_logits = out + (size_t)NN * HID;  // [N,40]

    float *pCsrc, *pCdst, *pB;
    __half* pH;
    int *pCntS, *pCntD, *pRow, *pPos, *pBsum, *pEsrc;
    cudaGetSymbolAddress((void**)&pCsrc, g_csrc);
    cudaGetSymbolAddress((void**)&pCdst, g_cdst);
    cudaGetSymbolAddress((void**)&pH, g_half);
    cudaGetSymbolAddress((void**)&pB, g_bufB);
    cudaGetSymbolAddress((void**)&pCntS, g_cnt_s);
    cudaGetSymbolAddress((void**)&pCntD, g_cnt_d);
    cudaGetSymbolAddress((void**)&pRow, g_rowptr);
    cudaGetSymbolAddress((void**)&pPos, g_pos);
    cudaGetSymbolAddress((void**)&pBsum, g_bsum);
    cudaGetSymbolAddress((void**)&pEsrc, g_esrc);

    const int TB = 256;

    // ---- degree norms + CSR build (once; shared by both layers) ----
    zeroi_kernel<<<(NN + TB - 1) / TB, TB>>>(pCntS, NN);
    zeroi_kernel<<<(NN + TB - 1) / TB, TB>>>(pCntD, NN);
    deg_kernel<<<(EE + TB - 1) / TB, TB>>>(src, dst, pCntS, pCntD, EE);
    norm_kernel<<<(NN + TB - 1) / TB, TB>>>(pCntS, pCntD, pCsrc, pCdst, NN);
    scan_local_kernel<<<NB_SCAN, 256>>>(pCntD, pRow, pBsum, NN);
    scan_bsum_kernel<<<1, 128>>>(pBsum, NB_SCAN);
    scan_add_kernel<<<(NN + TB - 1) / TB, TB>>>(pRow, pPos, pBsum, NN);
    fill_kernel<<<(EE + TB - 1) / TB, TB>>>(src, dst, pPos, pEsrc, EE);

    const int nmma = (NN + 127) / 128;       // 782
    const int nagg = (NN * 32 + TB - 1) / TB;
    const int ncls = (NN + 63) / 64;         // 1563

    // ---- layer 0: h16 = (x @ W0)*c_src; bufB = relu(agg(h16)*c_dst + b0) ----
    mma_gemm_kernel<FIN, true><<<nmma, 256>>>(x, W0, pCsrc, pH, NN);
    agg_half_kernel<true><<<nagg, TB>>>(pH, pEsrc, pRow, pCdst, b0, pB, NN);

    // ---- layer 1: h16 = (bufB @ W1)*c_src; out_h = agg(h16)*c_dst + b1 ----
    mma_gemm_kernel<HID, true><<<nmma, 256>>>(pB, W1, pCsrc, pH, NN);
    agg_half_kernel<false><<<nagg, TB>>>(pH, pEsrc, pRow, pCdst, b1, out_h, NN);

    // ---- logits = relu(h) @ Wc + bc ----
    classifier_kernel<<<ncls, 320>>>(out_h, Wc, bc, out_logits, NN);
}